// round 6
// baseline (speedup 1.0000x reference)
#include <cuda_runtime.h>
#include <cuda_bf16.h>
#include <math.h>
#include <stdint.h>

#define NN 4096
#define KK 32
#define CC 128
#define VV 21
#define NTILE 1024          // NN/4 tiles of 128 rows
#define GRID 148            // 1 CTA per SM, persistent

// ---------------- precomputed tensors (device globals) ----------------
__device__ float g_base[CC];                        // bl2 + (c0@Wr2+br2) + be2
__device__ float g_u0[CC];                          // c0 @ Wl2[:C]
__device__ __nv_bfloat16 g_Tb[VV * CC];             // bf16(W_s[v] @ Wl2[C:])
__device__ float g_TW[VV][VV];                      // T @ W_out
__device__ float g_g0[VV];                          // (bl2+bo2)@W_out + b_out
__device__ float g_g1[VV];                          // u0@W_out
__device__ float g_key[NN];                         // (chain_M*mask+1e-4)*|z|
__device__ __align__(16) __nv_bfloat16 g_Bb[CC * CC]; // bf16(We2) [k][n]

// ---------------- PTX helpers (plain sm_103-legal only) ----------------
__device__ __forceinline__ uint32_t smem_u32(const void* p) {
    uint32_t a;
    asm("{ .reg .u64 t; cvta.to.shared.u64 t, %1; cvt.u32.u64 %0, t; }" : "=r"(a) : "l"(p));
    return a;
}
__device__ __forceinline__ void ldmx4(uint32_t* r, uint32_t p) {
    asm volatile("ldmatrix.sync.aligned.m8n8.x4.shared.b16 {%0,%1,%2,%3}, [%4];"
                 : "=r"(r[0]), "=r"(r[1]), "=r"(r[2]), "=r"(r[3]) : "r"(p));
}
__device__ __forceinline__ void ldmx4t(uint32_t* r, uint32_t p) {
    asm volatile("ldmatrix.sync.aligned.m8n8.x4.trans.shared.b16 {%0,%1,%2,%3}, [%4];"
                 : "=r"(r[0]), "=r"(r[1]), "=r"(r[2]), "=r"(r[3]) : "r"(p));
}
__device__ __forceinline__ void mma16816(float* d, const uint32_t* a, uint32_t b0, uint32_t b1) {
    asm volatile(
        "mma.sync.aligned.m16n8k16.row.col.f32.bf16.bf16.f32 "
        "{%0,%1,%2,%3}, {%4,%5,%6,%7}, {%8,%9}, {%0,%1,%2,%3};"
        : "+f"(d[0]), "+f"(d[1]), "+f"(d[2]), "+f"(d[3])
        : "r"(a[0]), "r"(a[1]), "r"(a[2]), "r"(a[3]), "r"(b0), "r"(b1));
}
__device__ __forceinline__ void cp16(uint32_t dst, const void* src) {
    asm volatile("cp.async.cg.shared.global [%0], [%1], 16;"
                 :: "r"(dst), "l"(src) : "memory");
}
__device__ __forceinline__ void cp_commit() {
    asm volatile("cp.async.commit_group;" ::: "memory");
}
__device__ __forceinline__ void cp_wait1() {
    asm volatile("cp.async.wait_group 1;" ::: "memory");
}

// ---------------- precompute kernel (grid=32, block=256) ----------------
__global__ void precompute_kernel(
    const float* __restrict__ bl1, const float* __restrict__ bo1,
    const float* __restrict__ Wl2, const float* __restrict__ bl2,
    const float* __restrict__ Wr2, const float* __restrict__ br2,
    const float* __restrict__ be2, const float* __restrict__ bo2,
    const float* __restrict__ We2,
    const float* __restrict__ W_s, const float* __restrict__ W_out,
    const float* __restrict__ b_out,
    const float* __restrict__ mask, const float* __restrict__ chain_M,
    const float* __restrict__ z)
{
    __shared__ float sh0[CC];
    __shared__ float sh1[CC];
    __shared__ float sh2[CC];
    const int b = blockIdx.x;
    const int t = threadIdx.x;

    {
        int i = b * 256 + t;
        if (i < NN) {
            float cm = __fadd_rn(__fmul_rn(chain_M[i], mask[i]), 1e-4f);
            g_key[i] = __fmul_rn(cm, fabsf(z[i]));
        }
    }
    for (int i = b * 256 + t; i < CC * CC; i += 32 * 256)
        g_Bb[i] = __float2bfloat16(We2[i]);

    if (b < VV) {
        if (t < CC) {
            float acc = 0.f;
            for (int hh = 0; hh < CC; hh++)
                acc += W_s[b * CC + hh] * Wl2[(CC + hh) * CC + t];
            g_Tb[b * CC + t] = __float2bfloat16(acc);
            sh0[t] = acc;
        }
        __syncthreads();
        if (t < VV) {
            float acc = 0.f;
            for (int c = 0; c < CC; c++)
                acc += sh0[c] * W_out[c * VV + t];
            g_TW[b][t] = acc;
        }
    } else if (b == VV) {
        if (t < CC) sh0[t] = bl1[t] + bo1[t];          // c0
        __syncthreads();
        if (t < CC) {
            float u = 0.f, r = 0.f;
            for (int d = 0; d < CC; d++) {
                float c0 = sh0[d];
                u += c0 * Wl2[d * CC + t];
                r += c0 * Wr2[d * CC + t];
            }
            sh1[t] = u;  g_u0[t] = u;
            g_base[t] = bl2[t] + r + br2[t] + be2[t];
            sh2[t] = bl2[t] + bo2[t];
        }
        __syncthreads();
        if (t < VV) {
            float a0 = b_out[t], a1 = 0.f;
            for (int c = 0; c < CC; c++) {
                float wo = W_out[c * VV + t];
                a0 += sh2[c] * wo;
                a1 += sh1[c] * wo;
            }
            g_g0[t] = a0;
            g_g1[t] = a1;
        }
    }
}

// ---------------- main kernel smem ----------------
// A/B bf16 layout: 256B rows, 16B chunk j stored at j ^ (row & 7).
struct MetaBuf {
    float Am[4][KK];
    int   Sv[4][KK];
    float Mk[4];
    float Wv[4][VV];
};
struct Smem {
    __nv_bfloat16 B[CC * CC];     // 32 KB swizzled We2 bf16
    __nv_bfloat16 A[CC * CC];     // 32 KB swizzled E tile bf16
    float stage[2][CC * CC];      // 128 KB fp32 cp.async staging ring
    __nv_bfloat16 T2[VV * CC];
    float Base[CC], U0[CC], A2[CC];
    float G0[24], G1[24];
    float TW[VV][VV];
    MetaBuf mb[2];
    float Sc2[4][KK][2];          // per-node per-k partial scores (2 n-halves)
};

// ---------------- main fused kernel ----------------
// 256 threads / 8 warps, persistent. Warp w: node h = w>>1 (rows h*32..h*32+31),
// channel half n0 = (w&1)*64. Homogeneous: all warps issue cp.async, convert,
// GEMM; warps 0-3 run the final per-node epilogue.
__global__ void __launch_bounds__(256, 1) gat_mma_kernel(
    const float* __restrict__ E,
    const int*   __restrict__ E_idx,
    const int*   __restrict__ S,
    const float* __restrict__ mask,
    const float* __restrict__ a2,
    float*       __restrict__ out)
{
    extern __shared__ char raw[];
    Smem* sm = (Smem*)raw;

    const int t    = threadIdx.x;
    const int lane = t & 31;
    const int wid  = t >> 5;
    const int b    = blockIdx.x;
    const int niter = (NTILE - b + GRID - 1) / GRID;

    // ---- one-time setup: B + tables ----
    {
        const uint4* Bg = (const uint4*)g_Bb;
        #pragma unroll 2
        for (int i = t; i < 2048; i += 256) {
            int r = i >> 4, j = i & 15;
            *(uint4*)((char*)sm->B + r * 256 + ((j ^ (r & 7)) << 4)) = Bg[i];
        }
        for (int i = t; i < VV * CC; i += 256) sm->T2[i] = g_Tb[i];
        if (t < CC) {
            sm->Base[t] = g_base[t];
            sm->U0[t]   = g_u0[t];
            sm->A2[t]   = a2[t];
        }
        if (t < VV) { sm->G0[t] = g_g0[t]; sm->G1[t] = g_g1[t]; }
        for (int i = t; i < VV * VV; i += 256)
            sm->TW[i / VV][i % VV] = g_TW[i / VV][i % VV];
    }

    // ---- precomputed per-thread addresses ----
    const uint32_t Abase = smem_u32(sm->A);
    const uint32_t Bbase = smem_u32(sm->B);
    const uint32_t stg_u[2] = { smem_u32(sm->stage[0]), smem_u32(sm->stage[1]) };
    const int h   = wid >> 1;
    const int n0w = (wid & 1) * 64;

    // A ldmatrix: mt in {0,1}: row = h*32 + mt*16 + (lane&15), hi = lane>>4
    const int arow0 = h * 32 + (lane & 15);
    const int arow1 = arow0 + 16;
    const uint32_t aAddr0 = Abase + arow0 * 256;
    const uint32_t aAddr1 = Abase + arow1 * 256;
    const int rm0 = arow0 & 7, rm1 = arow1 & 7;
    const int ahi = lane >> 4;
    // B ldmatrix (trans): rlow = k-within-step, chunk = (w&1)*8 + p*2 + bhi
    const int bsub = lane >> 3;
    const int rlow = (bsub & 1) * 8 + (lane & 7);
    const int rb7  = rlow & 7;
    const int bhi  = bsub >> 1;
    const int pg2  = (wid & 1) * 8;
    const uint32_t bAddr = Bbase + rlow * 256;

    // ---- prologue: metadata + cp.async for tile b into stage 0 ----
    {
        const int tile = b;
        if (t < 128) {
            const int hh = t >> 5, k = t & 31;
            const int n = tile * 4 + hh;
            const int j = E_idx[n * KK + k];
            sm->mb[0].Sv[hh][k] = S[j];
            float kn = g_key[n], kj = g_key[j];
            float att = (kn > kj || (kn == kj && n > j)) ? 1.f : 0.f;
            sm->mb[0].Am[hh][k] = mask[n] * att;
        }
        if (t < 4) sm->mb[0].Mk[t] = mask[tile * 4 + t];
        for (int i = t; i < 4 * VV; i += 256) sm->mb[0].Wv[i / VV][i % VV] = 0.f;

        const float4* Eg = (const float4*)(E + (size_t)tile * (CC * CC));
        #pragma unroll
        for (int s = 0; s < 16; s++) {
            const int i = t + s * 256;
            cp16(stg_u[0] + (uint32_t)i * 16, &Eg[i]);
        }
        cp_commit();
    }

    for (int it = 0; it < niter; it++) {
        const int p    = it & 1;
        const int tile = b + it * GRID;
        const int next = tile + GRID;

        // ---- issue next tile (stage p^1, metadata mb[p^1]) ----
        if (next < NTILE) {
            if (t < 128) {
                const int hh = t >> 5, k = t & 31;
                const int n = next * 4 + hh;
                const int j = E_idx[n * KK + k];
                sm->mb[p ^ 1].Sv[hh][k] = S[j];
                float kn = g_key[n], kj = g_key[j];
                float att = (kn > kj || (kn == kj && n > j)) ? 1.f : 0.f;
                sm->mb[p ^ 1].Am[hh][k] = mask[n] * att;
            }
            if (t < 4) sm->mb[p ^ 1].Mk[t] = mask[next * 4 + t];
            for (int i = t; i < 4 * VV; i += 256)
                sm->mb[p ^ 1].Wv[i / VV][i % VV] = 0.f;

            const float4* Eg = (const float4*)(E + (size_t)next * (CC * CC));
            #pragma unroll
            for (int s = 0; s < 16; s++) {
                const int i = t + s * 256;
                cp16(stg_u[p ^ 1] + (uint32_t)i * 16, &Eg[i]);
            }
        }
        cp_commit();
        cp_wait1();            // tile `it` staged
        __syncthreads();       // visible to all; prev GEMM reads of A done

        // ---- convert stage[p] fp32 -> A bf16 (swizzled) ----
        {
            const float4* stg = (const float4*)sm->stage[p];
            char* Ab = (char*)sm->A;
            #pragma unroll
            for (int s = 0; s < 16; s++) {
                const int i = t + s * 256;
                float4 v = stg[i];
                const int r = i >> 5, q = i & 31;
                __nv_bfloat162 lo = __float22bfloat162_rn(make_float2(v.x, v.y));
                __nv_bfloat162 hi = __float22bfloat162_rn(make_float2(v.z, v.w));
                uint2 pk;
                pk.x = *(const uint32_t*)&lo;
                pk.y = *(const uint32_t*)&hi;
                *(uint2*)(Ab + r * 256 + (((q >> 1) ^ (r & 7)) << 4) + (q & 1) * 8) = pk;
            }
        }
        __syncthreads();

        MetaBuf* mb = &sm->mb[p];

        // ---- GEMM: warp tile 32x64, K=128 in 8 k-steps ----
        float acc[64];
        #pragma unroll
        for (int i = 0; i < 64; i++) acc[i] = 0.f;

        #pragma unroll
        for (int ks = 0; ks < 8; ks++) {
            uint32_t af0[4], af1[4];
            ldmx4(af0, aAddr0 + (((ks * 2 + ahi) ^ rm0) << 4));
            ldmx4(af1, aAddr1 + (((ks * 2 + ahi) ^ rm1) << 4));
            #pragma unroll
            for (int pp = 0; pp < 4; pp++) {
                uint32_t bf[4];
                ldmx4t(bf, bAddr + ks * 4096 + (((pg2 + pp * 2 + bhi) ^ rb7) << 4));
                mma16816(&acc[(2 * pp) * 4],          af0, bf[0], bf[1]);
                mma16816(&acc[(2 * pp + 1) * 4],      af0, bf[2], bf[3]);
                mma16816(&acc[32 + (2 * pp) * 4],     af1, bf[0], bf[1]);
                mma16816(&acc[32 + (2 * pp + 1) * 4], af1, bf[2], bf[3]);
            }
        }

        // ---- partial scores over this warp's 64 channels ----
        {
            const int gid = lane >> 2;
            const int qid = lane & 3;
            const float mk = mb->Mk[h];
            #pragma unroll
            for (int mt = 0; mt < 2; mt++) {
                const int klo = mt * 16 + gid;
                const int khi = klo + 8;
                const float aA_lo = mb->Am[h][klo];
                const float aA_hi = mb->Am[h][khi];
                const __nv_bfloat162* Tlo =
                    (const __nv_bfloat162*)&sm->T2[mb->Sv[h][klo] * CC];
                const __nv_bfloat162* Thi =
                    (const __nv_bfloat162*)&sm->T2[mb->Sv[h][khi] * CC];

                float s_lo = 0.f, s_hi = 0.f;
                #pragma unroll
                for (int pp = 0; pp < 4; pp++) {
                    #pragma unroll
                    for (int sub = 0; sub < 2; sub++) {
                        const int c0 = n0w + pp * 16 + sub * 8 + qid * 2;
                        const float bb0 = sm->Base[c0]     + mk * sm->U0[c0];
                        const float bb1 = sm->Base[c0 + 1] + mk * sm->U0[c0 + 1];
                        const float2 tl = __bfloat1622float2(Tlo[c0 >> 1]);
                        const float2 th = __bfloat1622float2(Thi[c0 >> 1]);
                        const float a20 = sm->A2[c0], a21 = sm->A2[c0 + 1];
                        const float* d = &acc[mt * 32 + (2 * pp + sub) * 4];

                        float p0 = d[0] + bb0 + aA_lo * tl.x;
                        float p1 = d[1] + bb1 + aA_lo * tl.y;
                        float p2 = d[2] + bb0 + aA_hi * th.x;
                        float p3 = d[3] + bb1 + aA_hi * th.y;
                        p0 = fmaxf(p0, 0.2f * p0);
                        p1 = fmaxf(p1, 0.2f * p1);
                        p2 = fmaxf(p2, 0.2f * p2);
                        p3 = fmaxf(p3, 0.2f * p3);
                        s_lo = fmaf(p0, a20, s_lo);
                        s_lo = fmaf(p1, a21, s_lo);
                        s_hi = fmaf(p2, a20, s_hi);
                        s_hi = fmaf(p3, a21, s_hi);
                    }
                }
                s_lo += __shfl_xor_sync(0xffffffffu, s_lo, 1);
                s_lo += __shfl_xor_sync(0xffffffffu, s_lo, 2);
                s_hi += __shfl_xor_sync(0xffffffffu, s_hi, 1);
                s_hi += __shfl_xor_sync(0xffffffffu, s_hi, 2);
                if (qid == 0) {
                    sm->Sc2[h][klo][wid & 1] = s_lo;
                    sm->Sc2[h][khi][wid & 1] = s_hi;
                }
            }
        }
        __syncthreads();

        // ---- softmax over k + 21-bin logits + log_softmax (warps 0-3) ----
        if (wid < 4) {
            const int n = tile * 4 + wid;
            const float aA = mb->Am[wid][lane];
            const int   sk = mb->Sv[wid][lane];

            float score = sm->Sc2[wid][lane][0] + sm->Sc2[wid][lane][1];
            float mx = score;
            #pragma unroll
            for (int o = 16; o > 0; o >>= 1)
                mx = fmaxf(mx, __shfl_xor_sync(0xffffffffu, mx, o));
            float e = expf(score - mx);
            float ssum = e;
            #pragma unroll
            for (int o = 16; o > 0; o >>= 1)
                ssum += __shfl_xor_sync(0xffffffffu, ssum, o);
            atomicAdd(&mb->Wv[wid][sk], (e / ssum) * aA);
            __syncwarp();

            float lg = -1e30f;
            if (lane < VV) {
                lg = sm->G0[lane] + mb->Mk[wid] * sm->G1[lane];
                #pragma unroll
                for (int u = 0; u < VV; u++)
                    lg = fmaf(mb->Wv[wid][u], sm->TW[u][lane], lg);
            }
            float mx2 = lg;
            #pragma unroll
            for (int o = 16; o > 0; o >>= 1)
                mx2 = fmaxf(mx2, __shfl_xor_sync(0xffffffffu, mx2, o));
            float e2 = (lane < VV) ? expf(lg - mx2) : 0.f;
            float s2 = e2;
            #pragma unroll
            for (int o = 16; o > 0; o >>= 1)
                s2 += __shfl_xor_sync(0xffffffffu, s2, o);
            if (lane < VV)
                out[n * VV + lane] = lg - mx2 - logf(s2);
        }
        __syncthreads();   // A, Sc2, mb[p] free for reuse
    }
}

// ---------------- launch ----------------
extern "C" void kernel_launch(void* const* d_in, const int* in_sizes, int n_in,
                              void* d_out, int out_size)
{
    const float* E       = (const float*)d_in[0];
    const int*   E_idx   = (const int*)  d_in[1];
    const int*   S       = (const int*)  d_in[2];
    const float* mask    = (const float*)d_in[3];
    const float* chain_M = (const float*)d_in[4];
    const float* z       = (const float*)d_in[5];
    const float* bl1     = (const float*)d_in[7];
    const float* bo1     = (const float*)d_in[13];
    const float* Wl2     = (const float*)d_in[14];
    const float* bl2     = (const float*)d_in[15];
    const float* Wr2     = (const float*)d_in[16];
    const float* br2     = (const float*)d_in[17];
    const float* We2     = (const float*)d_in[18];
    const float* be2     = (const float*)d_in[19];
    const float* a2      = (const float*)d_in[20];
    const float* bo2     = (const float*)d_in[21];
    const float* W_s     = (const float*)d_in[22];
    const float* W_out   = (const float*)d_in[23];
    const float* b_out   = (const float*)d_in[24];

    float* out = (float*)d_out;

    const int smem_bytes = (int)sizeof(Smem);
    cudaFuncSetAttribute(gat_mma_kernel,
                         cudaFuncAttributeMaxDynamicSharedMemorySize, smem_bytes);

    precompute_kernel<<<32, 256>>>(bl1, bo1, Wl2, bl2, Wr2, br2, be2, bo2, We2,
                                   W_s, W_out, b_out, mask, chain_M, z);
    gat_mma_kernel<<<GRID, 256, smem_bytes>>>(E, E_idx, S, mask, a2, out);
}